// round 1
// baseline (speedup 1.0000x reference)
#include <cuda_runtime.h>
#include <math.h>

// hidden_states: [16, 13, 512, 768] fp32, reduce over axis=2 (512)
// out: [16, 13, 2304] = concat(sum, std(ddof=1), max) along last axis.
//
// One thread per (b*l, h) column: 208 * 768 = 159744 threads.
// Consecutive lanes -> consecutive h -> fully coalesced 128B lines per warp
// at every seq step. Pure HBM stream, ~327 MB read once.

#define BL    208      // 16 * 13
#define SEQ   512
#define HID   768

__global__ void __launch_bounds__(256) meanstdmax_kernel(
    const float* __restrict__ in, float* __restrict__ out)
{
    int idx = blockIdx.x * blockDim.x + threadIdx.x;   // 0 .. BL*HID-1
    int h  = idx % HID;
    int bl = idx / HID;

    const float* p = in + (size_t)bl * SEQ * HID + h;

    float s  = 0.0f;
    float sq = 0.0f;
    float mx = -INFINITY;

    #pragma unroll 8
    for (int i = 0; i < SEQ; i++) {
        float v = __ldcs(p + (size_t)i * HID);   // streaming: no reuse, skip L2 persistence
        s  += v;
        sq += v * v;
        mx  = fmaxf(mx, v);
    }

    float mean = s * (1.0f / SEQ);
    float var  = (sq - s * mean) * (1.0f / (SEQ - 1));
    float sd   = sqrtf(fmaxf(var, 0.0f));

    float* o = out + (size_t)bl * (3 * HID);
    o[h]            = s;
    o[HID + h]      = sd;
    o[2 * HID + h]  = mx;
}

extern "C" void kernel_launch(void* const* d_in, const int* in_sizes, int n_in,
                              void* d_out, int out_size)
{
    const float* in = (const float*)d_in[0];
    float* out = (float*)d_out;

    const int total = BL * HID;          // 159744
    const int threads = 256;
    const int blocks = total / threads;  // 624
    meanstdmax_kernel<<<blocks, threads>>>(in, out);
}

// round 2
// speedup vs baseline: 1.0170x; 1.0170x over previous
#include <cuda_runtime.h>
#include <math.h>

// hidden_states: [16, 13, 512, 768] fp32, reduce over axis=2 (512)
// out: [16, 13, 2304] = concat(sum, std(ddof=1), max) along last axis.
//
// One thread per (b*l, h) column: 208 * 768 = 159744 threads.
// Consecutive lanes -> consecutive h -> fully coalesced 128B lines per warp.
//
// R2 change: 64-thread blocks -> 2496 CTAs, all resident in one wave,
// per-SM CTA counts 16 or 17 (0.8% imbalance) instead of 4 or 5 (25%).

#define BL    208      // 16 * 13
#define SEQ   512
#define HID   768
#define TPB   64

__global__ void __launch_bounds__(TPB) meanstdmax_kernel(
    const float* __restrict__ in, float* __restrict__ out)
{
    int idx = blockIdx.x * TPB + threadIdx.x;   // 0 .. BL*HID-1
    int h  = idx % HID;
    int bl = idx / HID;

    const float* p = in + (size_t)bl * SEQ * HID + h;

    float s  = 0.0f;
    float sq = 0.0f;
    float mx = -INFINITY;

    #pragma unroll 8
    for (int i = 0; i < SEQ; i++) {
        float v = __ldcs(p + (size_t)i * HID);   // streaming: zero reuse
        s  += v;
        sq += v * v;
        mx  = fmaxf(mx, v);
    }

    float mean = s * (1.0f / SEQ);
    float var  = (sq - s * mean) * (1.0f / (SEQ - 1));
    float sd   = sqrtf(fmaxf(var, 0.0f));

    float* o = out + (size_t)bl * (3 * HID);
    o[h]            = s;
    o[HID + h]      = sd;
    o[2 * HID + h]  = mx;
}

extern "C" void kernel_launch(void* const* d_in, const int* in_sizes, int n_in,
                              void* d_out, int out_size)
{
    const float* in = (const float*)d_in[0];
    float* out = (float*)d_out;

    const int total = BL * HID;          // 159744
    const int blocks = total / TPB;      // 2496
    meanstdmax_kernel<<<blocks, TPB>>>(in, out);
}